// round 5
// baseline (speedup 1.0000x reference)
#include <cuda_runtime.h>

// Local cost volume (SpatialCorrelationSampler, kernel_size=1, patch 9x9):
// out[b, p, y, x] = sum_c t1[b,c,y,x] * t2[b,c,y+di,x+dj],  p=(di+4)*9+(dj+4)
// Shapes: t1,t2 [4,128,128,256] f32 -> out [4,81,128,256] f32.
//
// Main kernel: block = (batch, y, x-tile of 128). 9 warps; warp w owns di=w-4.
// Lane owns 4 px. Packed fma.rn.f32x2. For ODD dj the accumulator basis is
// shifted +1 px so the B pairs land on the SAME aligned P[0..5] register pairs
// as even dj (no odd-pair packing at all). Epilogue realigns via shfl.up.
// Pixels x in {0,128} for odd dj have no left neighbor -> patched by a tiny
// second kernel. 3-stage cp.async pipeline, 3 CTAs/SM.

#define CH 128
#define HH 128
#define WW 256
#define MD 4
#define DD 9
#define CC 4
#define XT 128
#define T2C 136           // XT + 2*MD
#define HW (HH*WW)
#define NTHREADS 288
#define NCHUNK (CH / CC)  // 32
#define STAGES 3

#define T1_STG (CC * XT)        // 512 floats per stage
#define T2_STG (CC * DD * T2C)  // 4896 floats per stage
#define SMEM_BYTES (STAGES * (T1_STG + T2_STG) * 4)   // 64,896 B

typedef unsigned long long u64;

__device__ __forceinline__ u64 pk(float lo, float hi) {
    u64 r; asm("mov.b64 %0, {%1,%2};" : "=l"(r) : "f"(lo), "f"(hi)); return r;
}
__device__ __forceinline__ void fma2(u64 &d, u64 a, u64 b) {
    asm("fma.rn.f32x2 %0, %1, %2, %0;" : "+l"(d) : "l"(a), "l"(b));
}
__device__ __forceinline__ float2 upk(u64 v) {
    float lo, hi; asm("mov.b64 {%0,%1}, %2;" : "=f"(lo), "=f"(hi) : "l"(v));
    return make_float2(lo, hi);
}
__device__ __forceinline__ void cpasync16(unsigned smem_addr, const void* gptr) {
    asm volatile("cp.async.cg.shared.global [%0], [%1], 16;" ::
                 "r"(smem_addr), "l"(gptr));
}

__global__ __launch_bounds__(NTHREADS, 3)
void corr_volume_kernel(const float* __restrict__ t1,
                        const float* __restrict__ t2,
                        float* __restrict__ out)
{
    extern __shared__ float sm[];
    float* s_t1 = sm;                          // [STAGES][CC][XT]
    float* s_t2 = sm + STAGES * T1_STG;        // [STAGES][CC][DD][T2C]

    const int tid   = threadIdx.x;
    const int wid   = tid >> 5;                // 0..8 : di row
    const int lane  = tid & 31;
    const int blk   = blockIdx.x;              // 0..1023
    const int xt    = blk & 1;
    const int y     = (blk >> 1) & (HH - 1);
    const int batch = blk >> 8;
    const int x0    = xt * XT;

    const int gy = y + wid - MD;
    const bool vrow = (unsigned)gy < (unsigned)HH;   // warp-uniform
    const float* t2row = t2 + (size_t)batch * CH * HW + (size_t)(vrow ? gy : 0) * WW;
    const float* t1row = t1 + (size_t)batch * CH * HW + (size_t)y * WW;

    // valid halo 4-float chunks: [lo, lo+33); one pad chunk per row.
    const int lo = (xt == 0) ? 1 : 0;

    // ---- one-time zero of constant padding (all stages) ----
    {
        const float4 z = make_float4(0.f, 0.f, 0.f, 0.f);
        #pragma unroll
        for (int st = 0; st < STAGES; st++)
            #pragma unroll
            for (int cc = 0; cc < CC; cc++) {
                float* row = s_t2 + (size_t)st * T2_STG + (cc * DD + wid) * T2C;
                if (vrow) {
                    int hpad = (xt == 0) ? 0 : 33;
                    if (lane == 0) *(float4*)&row[4 * hpad] = z;
                } else {
                    *(float4*)&row[4 * lane] = z;
                    if (lane < 2) *(float4*)&row[4 * (32 + lane)] = z;
                }
            }
    }

    u64 acc[DD][2];
    #pragma unroll
    for (int d = 0; d < DD; d++) { acc[d][0] = 0ull; acc[d][1] = 0ull; }

    const int xl = lane * 4;

    unsigned t1dst = (unsigned)__cvta_generic_to_shared(&s_t1[wid * XT + xl]);
    unsigned t2dst = (unsigned)__cvta_generic_to_shared(
        s_t2 + (size_t)wid * T2C + 4 * (lo + lane));
    unsigned t2dst2 = (unsigned)__cvta_generic_to_shared(
        s_t2 + (size_t)wid * T2C + 4 * (lo + 32));

    auto issue = [&](int chunk) {
        const int c0 = chunk * CC;
        const int st = chunk % STAGES;
        if (wid < CC) {
            const float* src = t1row + (size_t)(c0 + wid) * HW + x0;
            cpasync16(t1dst + st * (T1_STG * 4), &src[xl]);
        }
        if (vrow) {
            const int gx0 = x0 - 4 + 4 * lo;
            #pragma unroll
            for (int cc = 0; cc < CC; cc++) {
                const float* src = t2row + (size_t)(c0 + cc) * HW + gx0;
                unsigned off = (unsigned)(st * T2_STG + cc * (DD * T2C)) * 4;
                cpasync16(t2dst + off, &src[4 * lane]);
                if (lane == 0) cpasync16(t2dst2 + off, &src[128]);
            }
        }
        asm volatile("cp.async.commit_group;");
    };

    issue(0);
    issue(1);

    for (int it = 0; it < NCHUNK; it++) {
        const int st = it % STAGES;
        if (it == NCHUNK - 1) asm volatile("cp.async.wait_group 0;");
        else                  asm volatile("cp.async.wait_group 1;");
        __syncthreads();                 // chunk `it` visible; stage (it+2)%3 free
        if (it + 2 < NCHUNK) issue(it + 2);

        const float* b_t1 = s_t1 + (size_t)st * T1_STG;
        const float* b_t2 = s_t2 + (size_t)st * T2_STG;

        #pragma unroll
        for (int cc = 0; cc < CC; cc++) {
            float4 a  = *(const float4*)&b_t1[cc * XT + xl];
            float  a4 = b_t1[cc * XT + xl + 4];   // lane31: garbage -> dropped half
            u64 A0 = pk(a.x, a.y), A1 = pk(a.z, a.w);   // aligned: free
            u64 S0 = pk(a.y, a.z), S1 = pk(a.w, a4);    // shifted: 4 movs

            const ulonglong2* tr = (const ulonglong2*)&b_t2[(cc * DD + wid) * T2C + xl];
            ulonglong2 w0 = tr[0], w1 = tr[1], w2 = tr[2];
            u64 P[6] = { w0.x, w0.y, w1.x, w1.y, w2.x, w2.y };

            // even dj (natural basis): pairs P[dj/2], P[dj/2+1]
            fma2(acc[0][0], A0, P[0]); fma2(acc[0][1], A1, P[1]);
            fma2(acc[2][0], A0, P[1]); fma2(acc[2][1], A1, P[2]);
            fma2(acc[4][0], A0, P[2]); fma2(acc[4][1], A1, P[3]);
            fma2(acc[6][0], A0, P[3]); fma2(acc[6][1], A1, P[4]);
            fma2(acc[8][0], A0, P[4]); fma2(acc[8][1], A1, P[5]);
            // odd dj (+1 shifted basis): pairs P[(dj+1)/2], P[(dj+1)/2+1]
            fma2(acc[1][0], S0, P[1]); fma2(acc[1][1], S1, P[2]);
            fma2(acc[3][0], S0, P[2]); fma2(acc[3][1], S1, P[3]);
            fma2(acc[5][0], S0, P[3]); fma2(acc[5][1], S1, P[4]);
            fma2(acc[7][0], S0, P[4]); fma2(acc[7][1], S1, P[5]);
        }
    }

    // ---- epilogue ----
    size_t obase = (((size_t)batch * 81 + (size_t)wid * DD) * HH + y) * WW + x0 + xl;
    #pragma unroll
    for (int dj = 0; dj < DD; dj++) {
        float2 p0 = upk(acc[dj][0]);
        float2 p1 = upk(acc[dj][1]);
        float4 o;
        if ((dj & 1) == 0) {
            o = make_float4(p0.x, p0.y, p1.x, p1.y);
        } else {
            // shifted basis: (c(x+1),c(x+2)),(c(x+3),c(x+4)); c(x) from lane-1
            float cprev = __shfl_up_sync(0xffffffffu, p1.y, 1);
            o = make_float4(cprev, p0.x, p0.y, p1.x);
            // lane 0: cprev garbage at px x0 in {0,128} -> patched by mini kernel
        }
        *(float4*)&out[obase + (size_t)dj * HW] = o;
    }
}

// Patch kernel: odd dj, x in {0,128} (the tile-left-edge pixels).
// block = (batch, y); warp wid = di; lane -> (task=lane/4, q=lane%3..)
__global__ __launch_bounds__(NTHREADS, 4)
void corr_edge_kernel(const float* __restrict__ t1,
                      const float* __restrict__ t2,
                      float* __restrict__ out)
{
    const int tid   = threadIdx.x;
    const int wid   = tid >> 5;              // di index 0..8
    const int lane  = tid & 31;
    const int y     = blockIdx.x & (HH - 1);
    const int batch = blockIdx.x >> 7;

    const int task = lane >> 2;              // 0..7
    const int q    = lane & 3;               // channel quarter
    const int dj   = 1 + 2 * (task & 3);     // 1,3,5,7
    const int x    = (task >> 2) * XT;       // 0 or 128

    const int gy = y + wid - MD;
    const int gx = x + dj - MD;

    float sum = 0.0f;
    if ((unsigned)gy < (unsigned)HH && (unsigned)gx < (unsigned)WW) {
        const float* p1 = t1 + ((size_t)batch * CH + q * 32) * HW + (size_t)y * WW + x;
        const float* p2 = t2 + ((size_t)batch * CH + q * 32) * HW + (size_t)gy * WW + gx;
        #pragma unroll 8
        for (int c = 0; c < 32; c++)
            sum = fmaf(p1[(size_t)c * HW], p2[(size_t)c * HW], sum);
    }
    sum += __shfl_xor_sync(0xffffffffu, sum, 1);
    sum += __shfl_xor_sync(0xffffffffu, sum, 2);

    if (q == 0)
        out[(((size_t)batch * 81 + wid * DD + dj) * HH + y) * WW + x] = sum;
}

extern "C" void kernel_launch(void* const* d_in, const int* in_sizes, int n_in,
                              void* d_out, int out_size)
{
    const float* t1 = (const float*)d_in[0];
    const float* t2 = (const float*)d_in[1];
    float* out = (float*)d_out;
    cudaFuncSetAttribute(corr_volume_kernel,
                         cudaFuncAttributeMaxDynamicSharedMemorySize, SMEM_BYTES);
    corr_volume_kernel<<<2 * 4 * HH, NTHREADS, SMEM_BYTES>>>(t1, t2, out);
    corr_edge_kernel<<<4 * HH, NTHREADS>>>(t1, t2, out);
}